// round 3
// baseline (speedup 1.0000x reference)
#include <cuda_runtime.h>
#include <math.h>

// Problem constants (fixed-shape problem)
#define NNODES 10000
#define NFACT  20000
#define SSEG   30000      // NNODES + NFACT
#define EEDGE  80000      // 4 * NFACT
#define SD     64         // STATE_DIM == MSG_DIM
#define HM     128        // HID_MSG == HID_RO
#define DIN    132        // 2*SD + 4
#define NSTEPS 10

// ---------------- persistent device scratch (no allocation allowed) ----------------
__device__ float g_h[SSEG * SD];
__device__ float g_c[SSEG * SD];
__device__ float g_nm[SSEG * SD];
__device__ float g_w1t[DIN * HM];        // [k=132][j=128]  = mp_w1^T
__device__ float g_w2t[HM * HM];         // [128][128]      = mp_w2^T
__device__ float g_w3t[HM * SD];         // [128][64]       = mp_w3^T
__device__ float g_wg[(2 * SD) * (4 * SD)]; // [128][256]: rows 0..63 = w_ih^T, 64..127 = w_hh^T
__device__ float g_bg[4 * SD];           // b_ih + b_hh
__device__ float g_ro1t[SD * HM];        // [64][128]       = ro_w1^T
__device__ float g_ro2t[HM * HM];        // [128][128]      = ro_w2^T

__device__ __forceinline__ float sigm(float x) { return 1.f / (1.f + __expf(-x)); }

__device__ __forceinline__ void fma8(float* a, float x, const float4 w0, const float4 w1) {
    a[0] = fmaf(x, w0.x, a[0]); a[1] = fmaf(x, w0.y, a[1]);
    a[2] = fmaf(x, w0.z, a[2]); a[3] = fmaf(x, w0.w, a[3]);
    a[4] = fmaf(x, w1.x, a[4]); a[5] = fmaf(x, w1.y, a[5]);
    a[6] = fmaf(x, w1.z, a[6]); a[7] = fmaf(x, w1.w, a[7]);
}

// Register-tiled GEMM: each thread computes NE rows x 8 cols.
// sIn: shared, row stride SX (floats, 16B aligned, odd float4 count -> conflict-free)
// Wt : global, layout [K][NJ]
template <int NE, int K, int NJ, int SX>
__device__ __forceinline__ void tile_gemm(const float* sIn, const float* __restrict__ Wt,
                                          int te, int tj, float acc[][8]) {
#pragma unroll
    for (int i = 0; i < NE; i++)
#pragma unroll
        for (int j = 0; j < 8; j++) acc[i][j] = 0.f;
    const float* wbase = Wt + tj * 8;
#pragma unroll 2
    for (int k = 0; k < K; k += 4) {
        float4 xv[NE];
#pragma unroll
        for (int i = 0; i < NE; i++)
            xv[i] = *(const float4*)(sIn + (te * NE + i) * SX + k);
#pragma unroll
        for (int kk = 0; kk < 4; kk++) {
            float4 w0 = *(const float4*)(wbase + (k + kk) * NJ);
            float4 w1 = *(const float4*)(wbase + (k + kk) * NJ + 4);
#pragma unroll
            for (int i = 0; i < NE; i++) {
                float x = (&xv[i].x)[kk];
                fma8(acc[i], x, w0, w1);
            }
        }
    }
}

// ---------------- prep: transpose weights, combine LSTM biases ----------------
#define PREP_TOTAL (16896 + 16384 + 8192 + 16384 + 16384 + 256 + 8192 + 16384)
__global__ void k_prep(const float* __restrict__ w1, const float* __restrict__ w2,
                       const float* __restrict__ w3, const float* __restrict__ wih,
                       const float* __restrict__ whh, const float* __restrict__ bih,
                       const float* __restrict__ bhh, const float* __restrict__ r1,
                       const float* __restrict__ r2) {
    int i = blockIdx.x * 256 + threadIdx.x;
    if (i < 16896) { int j = i / 132, k = i % 132; g_w1t[k * 128 + j] = w1[i]; return; }
    i -= 16896;
    if (i < 16384) { int j = i / 128, k = i % 128; g_w2t[k * 128 + j] = w2[i]; return; }
    i -= 16384;
    if (i < 8192)  { int j = i / 128, k = i % 128; g_w3t[k * 64 + j] = w3[i]; return; }
    i -= 8192;
    if (i < 16384) { int j = i / 64, k = i % 64; g_wg[k * 256 + j] = wih[i]; return; }
    i -= 16384;
    if (i < 16384) { int j = i / 64, k = i % 64; g_wg[(64 + k) * 256 + j] = whh[i]; return; }
    i -= 16384;
    if (i < 256)   { g_bg[i] = bih[i] + bhh[i]; return; }
    i -= 256;
    if (i < 8192)  { int j = i / 64, k = i % 64; g_ro1t[k * 128 + j] = r1[i]; return; }
    i -= 8192;
    if (i < 16384) { int j = i / 128, k = i % 128; g_ro2t[k * 128 + j] = r2[i]; return; }
}

__global__ void k_init() {
    int i = blockIdx.x * 256 + threadIdx.x;
    if (i < SSEG * SD) {
        g_c[i] = 0.f;
        int s = i >> 6, d = i & 63;
        g_h[i] = (s >= NNODES && d == 0) ? 1.f : 0.f;
    }
}

__global__ void k_zero_nm() {
    int i = blockIdx.x * 256 + threadIdx.x;
    if (i < SSEG * SD) g_nm[i] = 0.f;
}

// ---------------- edge MLP + scatter (32 edges / block, 128 threads) ----------------
__global__ __launch_bounds__(128) void k_edge(const int* __restrict__ row,
                                              const int* __restrict__ col,
                                              const float* __restrict__ ea,
                                              const float* __restrict__ b1,
                                              const float* __restrict__ b2,
                                              const float* __restrict__ b3) {
    __shared__ float sX[32 * 140];   // inputs (132 used) / reused as H2 output
    __shared__ float sH[32 * 132];   // H1
    __shared__ int sRow[32];
    __shared__ int sCol[32];
    const int tid = threadIdx.x;
    const int e0 = blockIdx.x * 32;

    if (tid < 32) sCol[tid] = col[e0 + tid];
    else if (tid < 64) sRow[tid - 32] = row[e0 + tid - 32];
    __syncthreads();

    // gather [h[row] | h[col]] (64+64 floats) per edge
    for (int u = tid; u < 32 * 32; u += 128) {
        int el = u >> 5, part = u & 31;
        const float* src = (part < 16) ? (g_h + sRow[el] * SD + part * 4)
                                       : (g_h + sCol[el] * SD + (part - 16) * 4);
        *(float4*)(sX + el * 140 + part * 4) = *(const float4*)src;
    }
    if (tid < 32)
        *(float4*)(sX + tid * 140 + 128) = *(const float4*)(ea + (size_t)(e0 + tid) * 4);
    __syncthreads();

    // layer 1: 132 -> 128, relu
    {
        const int te = tid & 7, tj = tid >> 3;
        float acc[4][8];
        tile_gemm<4, DIN, HM, 140>(sX, g_w1t, te, tj, acc);
        float4 bb0 = *(const float4*)(b1 + tj * 8);
        float4 bb1 = *(const float4*)(b1 + tj * 8 + 4);
        float bv[8] = {bb0.x, bb0.y, bb0.z, bb0.w, bb1.x, bb1.y, bb1.z, bb1.w};
#pragma unroll
        for (int i = 0; i < 4; i++) {
            float* dst = sH + (te * 4 + i) * 132 + tj * 8;
#pragma unroll
            for (int j = 0; j < 8; j++) dst[j] = fmaxf(acc[i][j] + bv[j], 0.f);
        }
    }
    __syncthreads();

    // layer 2: 128 -> 128, relu (output written into sX, stride 140)
    {
        const int te = tid & 7, tj = tid >> 3;
        float acc[4][8];
        tile_gemm<4, HM, HM, 132>(sH, g_w2t, te, tj, acc);
        float4 bb0 = *(const float4*)(b2 + tj * 8);
        float4 bb1 = *(const float4*)(b2 + tj * 8 + 4);
        float bv[8] = {bb0.x, bb0.y, bb0.z, bb0.w, bb1.x, bb1.y, bb1.z, bb1.w};
#pragma unroll
        for (int i = 0; i < 4; i++) {
            float* dst = sX + (te * 4 + i) * 140 + tj * 8;
#pragma unroll
            for (int j = 0; j < 8; j++) dst[j] = fmaxf(acc[i][j] + bv[j], 0.f);
        }
    }
    __syncthreads();

    // layer 3: 128 -> 64, + scatter-add into nm[col]
    {
        const int te = tid & 15, tj = tid >> 4;  // 16 x (2 edges), 8 x (8 outputs)
        float acc[2][8];
        tile_gemm<2, HM, SD, 140>(sX, g_w3t, te, tj, acc);
        float4 bb0 = *(const float4*)(b3 + tj * 8);
        float4 bb1 = *(const float4*)(b3 + tj * 8 + 4);
        float bv[8] = {bb0.x, bb0.y, bb0.z, bb0.w, bb1.x, bb1.y, bb1.z, bb1.w};
#pragma unroll
        for (int i = 0; i < 2; i++) {
            float* dst = g_nm + (size_t)sCol[te * 2 + i] * SD + tj * 8;
#pragma unroll
            for (int j = 0; j < 8; j++) atomicAdd(dst + j, acc[i][j] + bv[j]);
        }
    }
}

// ---------------- fused LSTM cell (16 segments / block, 256 threads) ----------------
__global__ __launch_bounds__(256) void k_lstm() {
    __shared__ float sX[16 * 132];   // [nm | h]
    __shared__ float sG[16 * 264];   // gates (256 used)
    const int tid = threadIdx.x;
    const int s0 = blockIdx.x * 16;

    for (int u = tid; u < 16 * 32; u += 256) {
        int el = u >> 5, part = u & 31;
        int s = s0 + el;
        float4 v = make_float4(0.f, 0.f, 0.f, 0.f);
        if (s < SSEG) {
            const float* src = (part < 16) ? (g_nm + (size_t)s * SD + part * 4)
                                           : (g_h + (size_t)s * SD + (part - 16) * 4);
            v = *(const float4*)src;
        }
        *(float4*)(sX + el * 132 + part * 4) = v;
    }
    __syncthreads();

    {
        const int te = tid & 7, tj = tid >> 3;  // 8 x (2 segs), 32 x (8 gates)
        float acc[2][8];
        tile_gemm<2, 2 * SD, 4 * SD, 132>(sX, g_wg, te, tj, acc);
        float4 bb0 = *(const float4*)(g_bg + tj * 8);
        float4 bb1 = *(const float4*)(g_bg + tj * 8 + 4);
        float bv[8] = {bb0.x, bb0.y, bb0.z, bb0.w, bb1.x, bb1.y, bb1.z, bb1.w};
#pragma unroll
        for (int i = 0; i < 2; i++)
#pragma unroll
            for (int j = 0; j < 8; j++)
                sG[(te * 2 + i) * 264 + tj * 8 + j] = acc[i][j] + bv[j];
    }
    __syncthreads();

    for (int u = tid; u < 16 * 64; u += 256) {
        int el = u >> 6, d = u & 63;
        int s = s0 + el;
        if (s < SSEG) {
            float gi = sG[el * 264 + d];
            float gf = sG[el * 264 + 64 + d];
            float gg = sG[el * 264 + 128 + d];
            float go = sG[el * 264 + 192 + d];
            float c = g_c[(size_t)s * SD + d];
            float cn = sigm(gf) * c + sigm(gi) * tanhf(gg);
            g_c[(size_t)s * SD + d] = cn;
            g_h[(size_t)s * SD + d] = sigm(go) * tanhf(cn);
        }
    }
}

// ---------------- readout MLP + softmax (32 nodes / block, 128 threads) ----------------
__global__ __launch_bounds__(128) void k_readout(const float* __restrict__ b1,
                                                 const float* __restrict__ b2,
                                                 const float* __restrict__ w3,
                                                 const float* __restrict__ b3,
                                                 float* __restrict__ out) {
    __shared__ float sX[32 * 68];
    __shared__ float sA[32 * 132];
    __shared__ float sB[32 * 132];
    const int tid = threadIdx.x;
    const int n0 = blockIdx.x * 32;

    for (int u = tid; u < 32 * 16; u += 128) {
        int el = u >> 4, part = u & 15;
        int n = n0 + el;
        float4 v = make_float4(0.f, 0.f, 0.f, 0.f);
        if (n < NNODES) v = *(const float4*)(g_h + (size_t)n * SD + part * 4);
        *(float4*)(sX + el * 68 + part * 4) = v;
    }
    __syncthreads();
    {
        const int te = tid & 7, tj = tid >> 3;
        float acc[4][8];
        tile_gemm<4, SD, HM, 68>(sX, g_ro1t, te, tj, acc);
        float4 bb0 = *(const float4*)(b1 + tj * 8);
        float4 bb1 = *(const float4*)(b1 + tj * 8 + 4);
        float bv[8] = {bb0.x, bb0.y, bb0.z, bb0.w, bb1.x, bb1.y, bb1.z, bb1.w};
#pragma unroll
        for (int i = 0; i < 4; i++) {
            float* dst = sA + (te * 4 + i) * 132 + tj * 8;
#pragma unroll
            for (int j = 0; j < 8; j++) dst[j] = fmaxf(acc[i][j] + bv[j], 0.f);
        }
    }
    __syncthreads();
    {
        const int te = tid & 7, tj = tid >> 3;
        float acc[4][8];
        tile_gemm<4, HM, HM, 132>(sA, g_ro2t, te, tj, acc);
        float4 bb0 = *(const float4*)(b2 + tj * 8);
        float4 bb1 = *(const float4*)(b2 + tj * 8 + 4);
        float bv[8] = {bb0.x, bb0.y, bb0.z, bb0.w, bb1.x, bb1.y, bb1.z, bb1.w};
#pragma unroll
        for (int i = 0; i < 4; i++) {
            float* dst = sB + (te * 4 + i) * 132 + tj * 8;
#pragma unroll
            for (int j = 0; j < 8; j++) dst[j] = fmaxf(acc[i][j] + bv[j], 0.f);
        }
    }
    __syncthreads();
    if (tid < 32) {
        int n = n0 + tid;
        if (n < NNODES) {
            float l0 = b3[0], l1 = b3[1];
            const float* x = sB + tid * 132;
#pragma unroll 4
            for (int k = 0; k < HM; k++) {
                l0 = fmaf(x[k], w3[k], l0);
                l1 = fmaf(x[k], w3[HM + k], l1);
            }
            float m = fmaxf(l0, l1);
            float e0 = expf(l0 - m), e1 = expf(l1 - m);
            float inv = 1.f / (e0 + e1);
            out[(size_t)n * 2 + 0] = e0 * inv;
            out[(size_t)n * 2 + 1] = e1 * inv;
        }
    }
}

// ---------------- launch ----------------
extern "C" void kernel_launch(void* const* d_in, const int* in_sizes, int n_in,
                              void* d_out, int out_size) {
    (void)out_size;
    // Inputs: row, col, edge_attr, [n_nodes, num_segments (maybe as size-1 tensors)], then params.
    int base = 3;
    if (n_in >= 21 && in_sizes[3] == 1 && in_sizes[4] == 1) base = 5;

    const int* row = (const int*)d_in[0];
    const int* col = (const int*)d_in[1];
    const float* ea = (const float*)d_in[2];
    const float* mp_w1 = (const float*)d_in[base + 0];
    const float* mp_b1 = (const float*)d_in[base + 1];
    const float* mp_w2 = (const float*)d_in[base + 2];
    const float* mp_b2 = (const float*)d_in[base + 3];
    const float* mp_w3 = (const float*)d_in[base + 4];
    const float* mp_b3 = (const float*)d_in[base + 5];
    const float* w_ih  = (const float*)d_in[base + 6];
    const float* w_hh  = (const float*)d_in[base + 7];
    const float* b_ih  = (const float*)d_in[base + 8];
    const float* b_hh  = (const float*)d_in[base + 9];
    const float* ro_w1 = (const float*)d_in[base + 10];
    const float* ro_b1 = (const float*)d_in[base + 11];
    const float* ro_w2 = (const float*)d_in[base + 12];
    const float* ro_b2 = (const float*)d_in[base + 13];
    const float* ro_w3 = (const float*)d_in[base + 14];
    const float* ro_b3 = (const float*)d_in[base + 15];
    float* out = (float*)d_out;

    k_prep<<<(PREP_TOTAL + 255) / 256, 256>>>(mp_w1, mp_w2, mp_w3, w_ih, w_hh,
                                              b_ih, b_hh, ro_w1, ro_w2);
    k_init<<<(SSEG * SD + 255) / 256, 256>>>();

    for (int t = 0; t < NSTEPS; t++) {
        k_zero_nm<<<(SSEG * SD + 255) / 256, 256>>>();
        k_edge<<<EEDGE / 32, 128>>>(row, col, ea, mp_b1, mp_b2, mp_b3);
        k_lstm<<<(SSEG + 15) / 16, 256>>>();
    }

    k_readout<<<(NNODES + 31) / 32, 128>>>(ro_b1, ro_b2, ro_w3, ro_b3, out);
}

// round 7
// speedup vs baseline: 1.5905x; 1.5905x over previous
#include <cuda_runtime.h>
#include <math.h>

// Problem constants (fixed-shape problem)
#define NNODES 10000
#define NFACT  20000
#define SSEG   30000      // NNODES + NFACT
#define EEDGE  80000      // 4 * NFACT
#define SD     64         // STATE_DIM == MSG_DIM
#define HM     128        // HID_MSG == HID_RO
#define DIN    132        // 2*SD + 4
#define NSTEPS 10

// ---------------- persistent device scratch (no allocation allowed) ----------------
__device__ float g_h[SSEG * SD];
__device__ float g_c[SSEG * SD];
__device__ float g_nm[SSEG * SD];
__device__ float g_w1t[DIN * HM];        // [k=132][j=128]  = mp_w1^T
__device__ float g_w2t[HM * HM];         // [128][128]      = mp_w2^T
__device__ float g_w3t[HM * SD];         // [128][64]       = mp_w3^T
__device__ float g_wg[(2 * SD) * (4 * SD)]; // [128][256]: rows 0..63 = w_ih^T, 64..127 = w_hh^T
__device__ float g_bg[4 * SD];           // b_ih + b_hh
__device__ float g_ro1t[SD * HM];        // [64][128]       = ro_w1^T
__device__ float g_ro2t[HM * HM];        // [128][128]      = ro_w2^T

__device__ __forceinline__ float sigm(float x) { return 1.f / (1.f + __expf(-x)); }

__device__ __forceinline__ void fma8(float* a, float x, const float4 w0, const float4 w1) {
    a[0] = fmaf(x, w0.x, a[0]); a[1] = fmaf(x, w0.y, a[1]);
    a[2] = fmaf(x, w0.z, a[2]); a[3] = fmaf(x, w0.w, a[3]);
    a[4] = fmaf(x, w1.x, a[4]); a[5] = fmaf(x, w1.y, a[5]);
    a[6] = fmaf(x, w1.z, a[6]); a[7] = fmaf(x, w1.w, a[7]);
}

// Register-tiled GEMM: each thread computes NE rows x 8 cols.
// Row assignment is INTERLEAVED: thread (te) handles rows te + i*NT, i=0..NE-1.
// This makes same-phase LDS addresses one row-stride apart -> conflict-free banks.
// sIn: shared, row stride SX floats (16B aligned). Wt: global, layout [K][NJ].
template <int NE, int NT, int K, int NJ, int SX>
__device__ __forceinline__ void tile_gemm(const float* sIn, const float* __restrict__ Wt,
                                          int te, int tj, float acc[][8]) {
#pragma unroll
    for (int i = 0; i < NE; i++)
#pragma unroll
        for (int j = 0; j < 8; j++) acc[i][j] = 0.f;
    const float* wbase = Wt + tj * 8;
#pragma unroll 2
    for (int k = 0; k < K; k += 4) {
        float4 xv[NE];
#pragma unroll
        for (int i = 0; i < NE; i++)
            xv[i] = *(const float4*)(sIn + (te + i * NT) * SX + k);
#pragma unroll
        for (int kk = 0; kk < 4; kk++) {
            float4 w0 = *(const float4*)(wbase + (k + kk) * NJ);
            float4 w1 = *(const float4*)(wbase + (k + kk) * NJ + 4);
#pragma unroll
            for (int i = 0; i < NE; i++) {
                float x = (&xv[i].x)[kk];
                fma8(acc[i], x, w0, w1);
            }
        }
    }
}

// ---------------- prep: transpose weights, combine LSTM biases ----------------
#define PREP_TOTAL (16896 + 16384 + 8192 + 16384 + 16384 + 256 + 8192 + 16384)
__global__ void k_prep(const float* __restrict__ w1, const float* __restrict__ w2,
                       const float* __restrict__ w3, const float* __restrict__ wih,
                       const float* __restrict__ whh, const float* __restrict__ bih,
                       const float* __restrict__ bhh, const float* __restrict__ r1,
                       const float* __restrict__ r2) {
    int i = blockIdx.x * 256 + threadIdx.x;
    if (i < 16896) { int j = i / 132, k = i % 132; g_w1t[k * 128 + j] = w1[i]; return; }
    i -= 16896;
    if (i < 16384) { int j = i / 128, k = i % 128; g_w2t[k * 128 + j] = w2[i]; return; }
    i -= 16384;
    if (i < 8192)  { int j = i / 128, k = i % 128; g_w3t[k * 64 + j] = w3[i]; return; }
    i -= 8192;
    if (i < 16384) { int j = i / 64, k = i % 64; g_wg[k * 256 + j] = wih[i]; return; }
    i -= 16384;
    if (i < 16384) { int j = i / 64, k = i % 64; g_wg[(64 + k) * 256 + j] = whh[i]; return; }
    i -= 16384;
    if (i < 256)   { g_bg[i] = bih[i] + bhh[i]; return; }
    i -= 256;
    if (i < 8192)  { int j = i / 64, k = i % 64; g_ro1t[k * 128 + j] = r1[i]; return; }
    i -= 8192;
    if (i < 16384) { int j = i / 128, k = i % 128; g_ro2t[k * 128 + j] = r2[i]; return; }
}

__global__ void k_init() {
    int i = blockIdx.x * 256 + threadIdx.x;
    if (i < SSEG * SD) {
        g_c[i] = 0.f;
        g_nm[i] = 0.f;
        int s = i >> 6, d = i & 63;
        g_h[i] = (s >= NNODES && d == 0) ? 1.f : 0.f;
    }
}

// ---------------- edge MLP + scatter (32 edges / block, 128 threads) ----------------
__global__ __launch_bounds__(128, 6) void k_edge(const int* __restrict__ row,
                                                 const int* __restrict__ col,
                                                 const float* __restrict__ ea,
                                                 const float* __restrict__ b1,
                                                 const float* __restrict__ b2,
                                                 const float* __restrict__ b3) {
    __shared__ float sX[32 * 140];   // inputs (132 used) / reused as H2 output
    __shared__ float sH[32 * 132];   // H1
    __shared__ int sRow[32];
    __shared__ int sCol[32];
    const int tid = threadIdx.x;
    const int e0 = blockIdx.x * 32;

    if (tid < 32) sCol[tid] = col[e0 + tid];
    else if (tid < 64) sRow[tid - 32] = row[e0 + tid - 32];
    __syncthreads();

    // gather [h[row] | h[col]] (64+64 floats) per edge
    for (int u = tid; u < 32 * 32; u += 128) {
        int el = u >> 5, part = u & 31;
        const float* src = (part < 16) ? (g_h + sRow[el] * SD + part * 4)
                                       : (g_h + sCol[el] * SD + (part - 16) * 4);
        *(float4*)(sX + el * 140 + part * 4) = *(const float4*)src;
    }
    if (tid < 32)
        *(float4*)(sX + tid * 140 + 128) = *(const float4*)(ea + (size_t)(e0 + tid) * 4);
    __syncthreads();

    // layer 1: 132 -> 128, relu
    {
        const int te = tid & 7, tj = tid >> 3;
        float acc[4][8];
        tile_gemm<4, 8, DIN, HM, 140>(sX, g_w1t, te, tj, acc);
        float4 bb0 = *(const float4*)(b1 + tj * 8);
        float4 bb1 = *(const float4*)(b1 + tj * 8 + 4);
        float bv[8] = {bb0.x, bb0.y, bb0.z, bb0.w, bb1.x, bb1.y, bb1.z, bb1.w};
#pragma unroll
        for (int i = 0; i < 4; i++) {
            float* dst = sH + (te + i * 8) * 132 + tj * 8;
#pragma unroll
            for (int j = 0; j < 8; j++) dst[j] = fmaxf(acc[i][j] + bv[j], 0.f);
        }
    }
    __syncthreads();

    // layer 2: 128 -> 128, relu (output written into sX, stride 140)
    {
        const int te = tid & 7, tj = tid >> 3;
        float acc[4][8];
        tile_gemm<4, 8, HM, HM, 132>(sH, g_w2t, te, tj, acc);
        float4 bb0 = *(const float4*)(b2 + tj * 8);
        float4 bb1 = *(const float4*)(b2 + tj * 8 + 4);
        float bv[8] = {bb0.x, bb0.y, bb0.z, bb0.w, bb1.x, bb1.y, bb1.z, bb1.w};
#pragma unroll
        for (int i = 0; i < 4; i++) {
            float* dst = sX + (te + i * 8) * 140 + tj * 8;
#pragma unroll
            for (int j = 0; j < 8; j++) dst[j] = fmaxf(acc[i][j] + bv[j], 0.f);
        }
    }
    __syncthreads();

    // layer 3: 128 -> 64, + scatter-add into nm[col]
    {
        const int te = tid & 15, tj = tid >> 4;  // 16 x (2 edges), 8 x (8 outputs)
        float acc[2][8];
        tile_gemm<2, 16, HM, SD, 140>(sX, g_w3t, te, tj, acc);
        float4 bb0 = *(const float4*)(b3 + tj * 8);
        float4 bb1 = *(const float4*)(b3 + tj * 8 + 4);
        float bv[8] = {bb0.x, bb0.y, bb0.z, bb0.w, bb1.x, bb1.y, bb1.z, bb1.w};
#pragma unroll
        for (int i = 0; i < 2; i++) {
            float* dst = g_nm + (size_t)sCol[te + i * 16] * SD + tj * 8;
#pragma unroll
            for (int j = 0; j < 8; j++) atomicAdd(dst + j, acc[i][j] + bv[j]);
        }
    }
}

// ---------------- fused LSTM cell + nm re-zero (16 segments / block, 256 threads) ----
__global__ __launch_bounds__(256) void k_lstm() {
    __shared__ float sX[16 * 132];   // [nm | h]
    __shared__ float sG[16 * 264];   // gates (256 used)
    const int tid = threadIdx.x;
    const int s0 = blockIdx.x * 16;  // SSEG % 16 == 0 -> no tail

    for (int u = tid; u < 16 * 32; u += 256) {
        int el = u >> 5, part = u & 31;
        int s = s0 + el;
        const float* src = (part < 16) ? (g_nm + (size_t)s * SD + part * 4)
                                       : (g_h + (size_t)s * SD + (part - 16) * 4);
        *(float4*)(sX + el * 132 + part * 4) = *(const float4*)src;
    }
    __syncthreads();

    // re-zero the nm rows we just consumed (replaces the separate zero kernel)
    {
        int el = tid >> 4, part = tid & 15;  // 256 threads = 16 segs x 16 float4
        *(float4*)(g_nm + (size_t)(s0 + el) * SD + part * 4) =
            make_float4(0.f, 0.f, 0.f, 0.f);
    }

    {
        const int te = tid & 7, tj = tid >> 3;  // 8 x (2 segs), 32 x (8 gates)
        float acc[2][8];
        tile_gemm<2, 8, 2 * SD, 4 * SD, 132>(sX, g_wg, te, tj, acc);
        float4 bb0 = *(const float4*)(g_bg + tj * 8);
        float4 bb1 = *(const float4*)(g_bg + tj * 8 + 4);
        float bv[8] = {bb0.x, bb0.y, bb0.z, bb0.w, bb1.x, bb1.y, bb1.z, bb1.w};
#pragma unroll
        for (int i = 0; i < 2; i++)
#pragma unroll
            for (int j = 0; j < 8; j++)
                sG[(te + i * 8) * 264 + tj * 8 + j] = acc[i][j] + bv[j];
    }
    __syncthreads();

    for (int u = tid; u < 16 * 64; u += 256) {
        int el = u >> 6, d = u & 63;
        int s = s0 + el;
        float gi = sG[el * 264 + d];
        float gf = sG[el * 264 + 64 + d];
        float gg = sG[el * 264 + 128 + d];
        float go = sG[el * 264 + 192 + d];
        float c = g_c[(size_t)s * SD + d];
        float cn = sigm(gf) * c + sigm(gi) * tanhf(gg);
        g_c[(size_t)s * SD + d] = cn;
        g_h[(size_t)s * SD + d] = sigm(go) * tanhf(cn);
    }
}

// ---------------- readout MLP + softmax (32 nodes / block, 128 threads) ----------------
__global__ __launch_bounds__(128) void k_readout(const float* __restrict__ b1,
                                                 const float* __restrict__ b2,
                                                 const float* __restrict__ w3,
                                                 const float* __restrict__ b3,
                                                 float* __restrict__ out) {
    __shared__ float sX[32 * 68];
    __shared__ float sA[32 * 132];
    __shared__ float sB[32 * 132];
    const int tid = threadIdx.x;
    const int n0 = blockIdx.x * 32;

    for (int u = tid; u < 32 * 16; u += 128) {
        int el = u >> 4, part = u & 15;
        int n = n0 + el;
        float4 v = make_float4(0.f, 0.f, 0.f, 0.f);
        if (n < NNODES) v = *(const float4*)(g_h + (size_t)n * SD + part * 4);
        *(float4*)(sX + el * 68 + part * 4) = v;
    }
    __syncthreads();
    {
        const int te = tid & 7, tj = tid >> 3;
        float acc[4][8];
        tile_gemm<4, 8, SD, HM, 68>(sX, g_ro1t, te, tj, acc);
        float4 bb0 = *(const float4*)(b1 + tj * 8);
        float4 bb1 = *(const float4*)(b1 + tj * 8 + 4);
        float bv[8] = {bb0.x, bb0.y, bb0.z, bb0.w, bb1.x, bb1.y, bb1.z, bb1.w};
#pragma unroll
        for (int i = 0; i < 4; i++) {
            float* dst = sA + (te + i * 8) * 132 + tj * 8;
#pragma unroll
            for (int j = 0; j < 8; j++) dst[j] = fmaxf(acc[i][j] + bv[j], 0.f);
        }
    }
    __syncthreads();
    {
        const int te = tid & 7, tj = tid >> 3;
        float acc[4][8];
        tile_gemm<4, 8, HM, HM, 132>(sA, g_ro2t, te, tj, acc);
        float4 bb0 = *(const float4*)(b2 + tj * 8);
        float4 bb1 = *(const float4*)(b2 + tj * 8 + 4);
        float bv[8] = {bb0.x, bb0.y, bb0.z, bb0.w, bb1.x, bb1.y, bb1.z, bb1.w};
#pragma unroll
        for (int i = 0; i < 4; i++) {
            float* dst = sB + (te + i * 8) * 132 + tj * 8;
#pragma unroll
            for (int j = 0; j < 8; j++) dst[j] = fmaxf(acc[i][j] + bv[j], 0.f);
        }
    }
    __syncthreads();
    if (tid < 32) {
        int n = n0 + tid;
        if (n < NNODES) {
            float l0 = b3[0], l1 = b3[1];
            const float* x = sB + tid * 132;
#pragma unroll 4
            for (int k = 0; k < HM; k++) {
                l0 = fmaf(x[k], w3[k], l0);
                l1 = fmaf(x[k], w3[HM + k], l1);
            }
            float m = fmaxf(l0, l1);
            float e0 = expf(l0 - m), e1 = expf(l1 - m);
            float inv = 1.f / (e0 + e1);
            out[(size_t)n * 2 + 0] = e0 * inv;
            out[(size_t)n * 2 + 1] = e1 * inv;
        }
    }
}

// ---------------- launch ----------------
extern "C" void kernel_launch(void* const* d_in, const int* in_sizes, int n_in,
                              void* d_out, int out_size) {
    (void)out_size;
    // Inputs: row, col, edge_attr, [n_nodes, num_segments (maybe as size-1 tensors)], then params.
    int base = 3;
    if (n_in >= 21 && in_sizes[3] == 1 && in_sizes[4] == 1) base = 5;

    const int* row = (const int*)d_in[0];
    const int* col = (const int*)d_in[1];
    const float* ea = (const float*)d_in[2];
    const float* mp_w1 = (const float*)d_in[base + 0];
    const float* mp_b1 = (const float*)d_in[base + 1];
    const float* mp_w2 = (const float*)d_in[base + 2];
    const float* mp_b2 = (const float*)d_in[base + 3];
    const float* mp_w3 = (const float*)d_in[base + 4];
    const float* mp_b3 = (const float*)d_in[base + 5];
    const float* w_ih  = (const float*)d_in[base + 6];
    const float* w_hh  = (const float*)d_in[base + 7];
    const float* b_ih  = (const float*)d_in[base + 8];
    const float* b_hh  = (const float*)d_in[base + 9];
    const float* ro_w1 = (const float*)d_in[base + 10];
    const float* ro_b1 = (const float*)d_in[base + 11];
    const float* ro_w2 = (const float*)d_in[base + 12];
    const float* ro_b2 = (const float*)d_in[base + 13];
    const float* ro_w3 = (const float*)d_in[base + 14];
    const float* ro_b3 = (const float*)d_in[base + 15];
    float* out = (float*)d_out;

    k_prep<<<(PREP_TOTAL + 255) / 256, 256>>>(mp_w1, mp_w2, mp_w3, w_ih, w_hh,
                                              b_ih, b_hh, ro_w1, ro_w2);
    k_init<<<(SSEG * SD + 255) / 256, 256>>>();

    for (int t = 0; t < NSTEPS; t++) {
        k_edge<<<EEDGE / 32, 128>>>(row, col, ea, mp_b1, mp_b2, mp_b3);
        k_lstm<<<SSEG / 16, 256>>>();
    }

    k_readout<<<(NNODES + 31) / 32, 128>>>(ro_b1, ro_b2, ro_w3, ro_b3, out);
}

// round 8
// speedup vs baseline: 1.5982x; 1.0048x over previous
#include <cuda_runtime.h>
#include <math.h>

// Problem constants (fixed-shape problem)
#define NNODES 10000
#define NFACT  20000
#define SSEG   30000      // NNODES + NFACT
#define EEDGE  80000      // 4 * NFACT
#define SD     64         // STATE_DIM == MSG_DIM
#define HM     128        // HID_MSG == HID_RO
#define DIN    132        // 2*SD + 4
#define NSTEPS 10
#define WPAD   264        // weight array over-read pad for pipelined prefetch

// ---------------- persistent device scratch (no allocation allowed) ----------------
__device__ float g_h[SSEG * SD];
__device__ float g_c[SSEG * SD];
__device__ float g_nm[SSEG * SD];
__device__ float g_w1t[DIN * HM + WPAD];        // [k=132][j=128]  = mp_w1^T
__device__ float g_w2t[HM * HM + WPAD];         // [128][128]      = mp_w2^T
__device__ float g_w3t[HM * SD + WPAD];         // [128][64]       = mp_w3^T
__device__ float g_wg[(2 * SD) * (4 * SD) + WPAD]; // [128][256]: rows 0..63 = w_ih^T, 64..127 = w_hh^T
__device__ float g_bg[4 * SD];                  // b_ih + b_hh
__device__ float g_ro1t[SD * HM + WPAD];        // [64][128]       = ro_w1^T
__device__ float g_ro2t[HM * HM + WPAD];        // [128][128]      = ro_w2^T

__device__ __forceinline__ float sigm(float x) { return 1.f / (1.f + __expf(-x)); }

__device__ __forceinline__ void fma8(float* a, float x, const float4 w0, const float4 w1) {
    a[0] = fmaf(x, w0.x, a[0]); a[1] = fmaf(x, w0.y, a[1]);
    a[2] = fmaf(x, w0.z, a[2]); a[3] = fmaf(x, w0.w, a[3]);
    a[4] = fmaf(x, w1.x, a[4]); a[5] = fmaf(x, w1.y, a[5]);
    a[6] = fmaf(x, w1.z, a[6]); a[7] = fmaf(x, w1.w, a[7]);
}

// Register-tiled GEMM with explicit 1-deep software pipeline.
// Each thread computes NE interleaved rows (te + i*NT) x 8 cols.
// Next k-step's weights + next 4-k activation chunk are loaded BEFORE the
// current FFMAs, hiding LDG/LDS latency behind compute.
// Over-reads: sIn rows must have >=4 floats of stride slack past K (they do);
// Wt must be padded by >= NJ+8 floats (WPAD=264 covers all layers).
template <int NE, int NT, int K, int NJ, int SX>
__device__ __forceinline__ void tile_gemm(const float* sIn, const float* __restrict__ Wt,
                                          int te, int tj, float acc[][8]) {
#pragma unroll
    for (int i = 0; i < NE; i++)
#pragma unroll
        for (int j = 0; j < 8; j++) acc[i][j] = 0.f;
    const float* wp = Wt + tj * 8;
    float4 xv[NE];
#pragma unroll
    for (int i = 0; i < NE; i++)
        xv[i] = *(const float4*)(sIn + (te + i * NT) * SX);
    float4 w0 = *(const float4*)(wp);
    float4 w1 = *(const float4*)(wp + 4);
#pragma unroll 2
    for (int k = 0; k < K; k += 4) {
        float4 xn[NE];
#pragma unroll
        for (int i = 0; i < NE; i++)
            xn[i] = *(const float4*)(sIn + (te + i * NT) * SX + k + 4);
#pragma unroll
        for (int kk = 0; kk < 4; kk++) {
            float4 nw0 = *(const float4*)(wp + (k + kk + 1) * NJ);
            float4 nw1 = *(const float4*)(wp + (k + kk + 1) * NJ + 4);
#pragma unroll
            for (int i = 0; i < NE; i++)
                fma8(acc[i], (&xv[i].x)[kk], w0, w1);
            w0 = nw0; w1 = nw1;
        }
#pragma unroll
        for (int i = 0; i < NE; i++) xv[i] = xn[i];
    }
}

// ---------------- prep: transpose weights, combine LSTM biases ----------------
#define PREP_TOTAL (16896 + 16384 + 8192 + 16384 + 16384 + 256 + 8192 + 16384)
__global__ void k_prep(const float* __restrict__ w1, const float* __restrict__ w2,
                       const float* __restrict__ w3, const float* __restrict__ wih,
                       const float* __restrict__ whh, const float* __restrict__ bih,
                       const float* __restrict__ bhh, const float* __restrict__ r1,
                       const float* __restrict__ r2) {
    int i = blockIdx.x * 256 + threadIdx.x;
    if (i < 16896) { int j = i / 132, k = i % 132; g_w1t[k * 128 + j] = w1[i]; return; }
    i -= 16896;
    if (i < 16384) { int j = i / 128, k = i % 128; g_w2t[k * 128 + j] = w2[i]; return; }
    i -= 16384;
    if (i < 8192)  { int j = i / 128, k = i % 128; g_w3t[k * 64 + j] = w3[i]; return; }
    i -= 8192;
    if (i < 16384) { int j = i / 64, k = i % 64; g_wg[k * 256 + j] = wih[i]; return; }
    i -= 16384;
    if (i < 16384) { int j = i / 64, k = i % 64; g_wg[(64 + k) * 256 + j] = whh[i]; return; }
    i -= 16384;
    if (i < 256)   { g_bg[i] = bih[i] + bhh[i]; return; }
    i -= 256;
    if (i < 8192)  { int j = i / 64, k = i % 64; g_ro1t[k * 128 + j] = r1[i]; return; }
    i -= 8192;
    if (i < 16384) { int j = i / 128, k = i % 128; g_ro2t[k * 128 + j] = r2[i]; return; }
}

__global__ void k_init() {
    int i = blockIdx.x * 256 + threadIdx.x;
    if (i < SSEG * SD) {
        g_c[i] = 0.f;
        g_nm[i] = 0.f;
        int s = i >> 6, d = i & 63;
        g_h[i] = (s >= NNODES && d == 0) ? 1.f : 0.f;
    }
}

// ---------------- edge MLP + scatter (32 edges / block, 128 threads) ----------------
__global__ __launch_bounds__(128, 5) void k_edge(const int* __restrict__ row,
                                                 const int* __restrict__ col,
                                                 const float* __restrict__ ea,
                                                 const float* __restrict__ b1,
                                                 const float* __restrict__ b2,
                                                 const float* __restrict__ b3) {
    __shared__ float sX[32 * 140];   // inputs (132 used) / reused as H2 output
    __shared__ float sH[32 * 132];   // H1
    __shared__ int sRow[32];
    __shared__ int sCol[32];
    const int tid = threadIdx.x;
    const int e0 = blockIdx.x * 32;

    if (tid < 32) sCol[tid] = col[e0 + tid];
    else if (tid < 64) sRow[tid - 32] = row[e0 + tid - 32];
    __syncthreads();

    // gather [h[row] | h[col]] (64+64 floats) per edge
    for (int u = tid; u < 32 * 32; u += 128) {
        int el = u >> 5, part = u & 31;
        const float* src = (part < 16) ? (g_h + sRow[el] * SD + part * 4)
                                       : (g_h + sCol[el] * SD + (part - 16) * 4);
        *(float4*)(sX + el * 140 + part * 4) = *(const float4*)src;
    }
    if (tid < 32)
        *(float4*)(sX + tid * 140 + 128) = *(const float4*)(ea + (size_t)(e0 + tid) * 4);
    __syncthreads();

    // layer 1: 132 -> 128, relu
    {
        const int te = tid & 7, tj = tid >> 3;
        float acc[4][8];
        tile_gemm<4, 8, DIN, HM, 140>(sX, g_w1t, te, tj, acc);
        float4 bb0 = *(const float4*)(b1 + tj * 8);
        float4 bb1 = *(const float4*)(b1 + tj * 8 + 4);
        float bv[8] = {bb0.x, bb0.y, bb0.z, bb0.w, bb1.x, bb1.y, bb1.z, bb1.w};
#pragma unroll
        for (int i = 0; i < 4; i++) {
            float* dst = sH + (te + i * 8) * 132 + tj * 8;
#pragma unroll
            for (int j = 0; j < 8; j++) dst[j] = fmaxf(acc[i][j] + bv[j], 0.f);
        }
    }
    __syncthreads();

    // layer 2: 128 -> 128, relu (output written into sX, stride 140)
    {
        const int te = tid & 7, tj = tid >> 3;
        float acc[4][8];
        tile_gemm<4, 8, HM, HM, 132>(sH, g_w2t, te, tj, acc);
        float4 bb0 = *(const float4*)(b2 + tj * 8);
        float4 bb1 = *(const float4*)(b2 + tj * 8 + 4);
        float bv[8] = {bb0.x, bb0.y, bb0.z, bb0.w, bb1.x, bb1.y, bb1.z, bb1.w};
#pragma unroll
        for (int i = 0; i < 4; i++) {
            float* dst = sX + (te + i * 8) * 140 + tj * 8;
#pragma unroll
            for (int j = 0; j < 8; j++) dst[j] = fmaxf(acc[i][j] + bv[j], 0.f);
        }
    }
    __syncthreads();

    // layer 3: 128 -> 64, + scatter-add into nm[col]
    {
        const int te = tid & 15, tj = tid >> 4;  // 16 x (2 edges), 8 x (8 outputs)
        float acc[2][8];
        tile_gemm<2, 16, HM, SD, 140>(sX, g_w3t, te, tj, acc);
        float4 bb0 = *(const float4*)(b3 + tj * 8);
        float4 bb1 = *(const float4*)(b3 + tj * 8 + 4);
        float bv[8] = {bb0.x, bb0.y, bb0.z, bb0.w, bb1.x, bb1.y, bb1.z, bb1.w};
#pragma unroll
        for (int i = 0; i < 2; i++) {
            float* dst = g_nm + (size_t)sCol[te + i * 16] * SD + tj * 8;
#pragma unroll
            for (int j = 0; j < 8; j++) atomicAdd(dst + j, acc[i][j] + bv[j]);
        }
    }
}

// ---------------- fused LSTM cell + nm re-zero (32 segments / block, 256 threads) ----
// sMem is aliased: sX (32x132, load+gemm phase) then sG (32x264, gates phase).
__global__ __launch_bounds__(256, 2) void k_lstm() {
    __shared__ float sMem[32 * 264];  // 33.8 KB
    float* const sX = sMem;
    float* const sG = sMem;
    const int tid = threadIdx.x;
    const int s0 = blockIdx.x * 32;

    // load [nm | h] for 32 segments (zero-pad tail)
    for (int u = tid; u < 32 * 32; u += 256) {
        int el = u >> 5, part = u & 31;
        int s = s0 + el;
        float4 v = make_float4(0.f, 0.f, 0.f, 0.f);
        if (s < SSEG) {
            const float* src = (part < 16) ? (g_nm + (size_t)s * SD + part * 4)
                                           : (g_h + (size_t)s * SD + (part - 16) * 4);
            v = *(const float4*)src;
        }
        *(float4*)(sX + el * 132 + part * 4) = v;
    }
    __syncthreads();

    // re-zero the nm rows we just consumed (replaces a separate zero kernel)
    for (int u = tid; u < 32 * 16; u += 256) {
        int el = u >> 4, part = u & 15;
        int s = s0 + el;
        if (s < SSEG)
            *(float4*)(g_nm + (size_t)s * SD + part * 4) = make_float4(0.f, 0.f, 0.f, 0.f);
    }

    // gates GEMM: [32 x 128] @ [128 x 256]
    const int te = tid & 7, tj = tid >> 3;  // 8 x (4 segs), 32 x (8 gate cols)
    float acc[4][8];
    tile_gemm<4, 8, 2 * SD, 4 * SD, 132>(sX, g_wg, te, tj, acc);
    float4 bb0 = *(const float4*)(g_bg + tj * 8);
    float4 bb1 = *(const float4*)(g_bg + tj * 8 + 4);
    float bv[8] = {bb0.x, bb0.y, bb0.z, bb0.w, bb1.x, bb1.y, bb1.z, bb1.w};

    __syncthreads();  // all sX reads complete before overwriting the buffer as sG
#pragma unroll
    for (int i = 0; i < 4; i++)
#pragma unroll
        for (int j = 0; j < 8; j++)
            sG[(te + i * 8) * 264 + tj * 8 + j] = acc[i][j] + bv[j];
    __syncthreads();

    for (int u = tid; u < 32 * 64; u += 256) {
        int el = u >> 6, d = u & 63;
        int s = s0 + el;
        if (s < SSEG) {
            float gi = sG[el * 264 + d];
            float gf = sG[el * 264 + 64 + d];
            float gg = sG[el * 264 + 128 + d];
            float go = sG[el * 264 + 192 + d];
            float c = g_c[(size_t)s * SD + d];
            float cn = sigm(gf) * c + sigm(gi) * tanhf(gg);
            g_c[(size_t)s * SD + d] = cn;
            g_h[(size_t)s * SD + d] = sigm(go) * tanhf(cn);
        }
    }
}

// ---------------- readout MLP + softmax (32 nodes / block, 128 threads) ----------------
__global__ __launch_bounds__(128) void k_readout(const float* __restrict__ b1,
                                                 const float* __restrict__ b2,
                                                 const float* __restrict__ w3,
                                                 const float* __restrict__ b3,
                                                 float* __restrict__ out) {
    __shared__ float sX[32 * 68];
    __shared__ float sA[32 * 132];
    __shared__ float sB[32 * 132];
    const int tid = threadIdx.x;
    const int n0 = blockIdx.x * 32;

    for (int u = tid; u < 32 * 16; u += 128) {
        int el = u >> 4, part = u & 15;
        int n = n0 + el;
        float4 v = make_float4(0.f, 0.f, 0.f, 0.f);
        if (n < NNODES) v = *(const float4*)(g_h + (size_t)n * SD + part * 4);
        *(float4*)(sX + el * 68 + part * 4) = v;
    }
    __syncthreads();
    {
        const int te = tid & 7, tj = tid >> 3;
        float acc[4][8];
        tile_gemm<4, 8, SD, HM, 68>(sX, g_ro1t, te, tj, acc);
        float4 bb0 = *(const float4*)(b1 + tj * 8);
        float4 bb1 = *(const float4*)(b1 + tj * 8 + 4);
        float bv[8] = {bb0.x, bb0.y, bb0.z, bb0.w, bb1.x, bb1.y, bb1.z, bb1.w};
#pragma unroll
        for (int i = 0; i < 4; i++) {
            float* dst = sA + (te + i * 8) * 132 + tj * 8;
#pragma unroll
            for (int j = 0; j < 8; j++) dst[j] = fmaxf(acc[i][j] + bv[j], 0.f);
        }
    }
    __syncthreads();
    {
        const int te = tid & 7, tj = tid >> 3;
        float acc[4][8];
        tile_gemm<4, 8, HM, HM, 132>(sA, g_ro2t, te, tj, acc);
        float4 bb0 = *(const float4*)(b2 + tj * 8);
        float4 bb1 = *(const float4*)(b2 + tj * 8 + 4);
        float bv[8] = {bb0.x, bb0.y, bb0.z, bb0.w, bb1.x, bb1.y, bb1.z, bb1.w};
#pragma unroll
        for (int i = 0; i < 4; i++) {
            float* dst = sB + (te + i * 8) * 132 + tj * 8;
#pragma unroll
            for (int j = 0; j < 8; j++) dst[j] = fmaxf(acc[i][j] + bv[j], 0.f);
        }
    }
    __syncthreads();
    if (tid < 32) {
        int n = n0 + tid;
        if (n < NNODES) {
            float l0 = b3[0], l1 = b3[1];
            const float* x = sB + tid * 132;
#pragma unroll 4
            for (int k = 0; k < HM; k++) {
                l0 = fmaf(x[k], w3[k], l0);
                l1 = fmaf(x[k], w3[HM + k], l1);
            }
            float m = fmaxf(l0, l1);
            float e0 = expf(l0 - m), e1 = expf(l1 - m);
            float inv = 1.f / (e0 + e1);
            out[(size_t)n * 2 + 0] = e0 * inv;
            out[(size_t)n * 2 + 1] = e1 * inv;
        }
    }
}

// ---------------- launch ----------------
extern "C" void kernel_launch(void* const* d_in, const int* in_sizes, int n_in,
                              void* d_out, int out_size) {
    (void)out_size;
    // Inputs: row, col, edge_attr, [n_nodes, num_segments (maybe as size-1 tensors)], then params.
    int base = 3;
    if (n_in >= 21 && in_sizes[3] == 1 && in_sizes[4] == 1) base = 5;

    const int* row = (const int*)d_in[0];
    const int* col = (const int*)d_in[1];
    const float* ea = (const float*)d_in[2];
    const float* mp_w1 = (const float*)d_in[base + 0];
    const float* mp_b1 = (const float*)d_in[base + 1];
    const float* mp_w2 = (const float*)d_in[base + 2];
    const float* mp_b2 = (const float*)d_in[base + 3];
    const float* mp_w3 = (const float*)d_in[base + 4];
    const float* mp_b3 = (const float*)d_in[base + 5];
    const float* w_ih  = (const float*)d_in[base + 6];
    const float* w_hh  = (const float*)d_in[base + 7];
    const float* b_ih  = (const float*)d_in[base + 8];
    const float* b_hh  = (const float*)d_in[base + 9];
    const float* ro_w1 = (const float*)d_in[base + 10];
    const float* ro_b1 = (const float*)d_in[base + 11];
    const float* ro_w2 = (const float*)d_in[base + 12];
    const float* ro_b2 = (const float*)d_in[base + 13];
    const float* ro_w3 = (const float*)d_in[base + 14];
    const float* ro_b3 = (const float*)d_in[base + 15];
    float* out = (float*)d_out;

    k_prep<<<(PREP_TOTAL + 255) / 256, 256>>>(mp_w1, mp_w2, mp_w3, w_ih, w_hh,
                                              b_ih, b_hh, ro_w1, ro_w2);
    k_init<<<(SSEG * SD + 255) / 256, 256>>>();

    for (int t = 0; t < NSTEPS; t++) {
        k_edge<<<EEDGE / 32, 128>>>(row, col, ea, mp_b1, mp_b2, mp_b3);
        k_lstm<<<(SSEG + 31) / 32, 256>>>();
    }

    k_readout<<<(NNODES + 31) / 32, 128>>>(ro_b1, ro_b2, ro_w3, ro_b3, out);
}

// round 9
// speedup vs baseline: 1.7112x; 1.0707x over previous
#include <cuda_runtime.h>
#include <math.h>

// Problem constants (fixed-shape problem)
#define NNODES 10000
#define NFACT  20000
#define SSEG   30000      // NNODES + NFACT
#define EEDGE  80000      // 4 * NFACT
#define SD     64         // STATE_DIM == MSG_DIM
#define HM     128        // HID_MSG == HID_RO
#define NSTEPS 10
#define WPAD   264

// ---------------- persistent device scratch (no allocation allowed) ----------------
__device__ float g_h[SSEG * SD];
__device__ float g_c[SSEG * SD];
__device__ float g_nm[SSEG * SD];
__device__ float g_p[SSEG * 256];               // [P1(128) | P2(128)] per segment
__device__ float g_eaw[EEDGE * HM];             // W1c @ edge_attr + b1, per edge (step-invariant)
__device__ float g_wp[SD * 256 + WPAD];         // [k=64][j=256]: j<128 -> W1a^T, j>=128 -> W1b^T
__device__ float g_w1ct[4 * HM];                // [k=4][j=128] = W1c^T
__device__ float g_w2t[HM * HM + WPAD];         // [128][128] = mp_w2^T
__device__ float g_w3t[HM * SD + WPAD];         // [128][64]  = mp_w3^T
__device__ float g_wg[(2 * SD) * (4 * SD) + WPAD]; // [128][256]: rows 0..63 w_ih^T, 64..127 w_hh^T
__device__ float g_bg[4 * SD];                  // b_ih + b_hh
__device__ float g_ro1t[SD * HM + WPAD];        // [64][128]  = ro_w1^T
__device__ float g_ro2t[HM * HM + WPAD];        // [128][128] = ro_w2^T

__device__ __forceinline__ float sigm(float x) { return 1.f / (1.f + __expf(-x)); }

__device__ __forceinline__ void fma8(float* a, float x, const float4 w0, const float4 w1) {
    a[0] = fmaf(x, w0.x, a[0]); a[1] = fmaf(x, w0.y, a[1]);
    a[2] = fmaf(x, w0.z, a[2]); a[3] = fmaf(x, w0.w, a[3]);
    a[4] = fmaf(x, w1.x, a[4]); a[5] = fmaf(x, w1.y, a[5]);
    a[6] = fmaf(x, w1.z, a[6]); a[7] = fmaf(x, w1.w, a[7]);
}

// Register-tiled GEMM (non-pipelined; we are FFMA-floor bound, occupancy hides latency).
// Each thread computes NE interleaved rows (te + i*NT) x 8 cols.
// sIn: shared, row stride SX floats. Wt: global, layout [K][NJ].
template <int NE, int NT, int K, int NJ, int SX>
__device__ __forceinline__ void tile_gemm(const float* sIn, const float* __restrict__ Wt,
                                          int te, int tj, float acc[][8]) {
#pragma unroll
    for (int i = 0; i < NE; i++)
#pragma unroll
        for (int j = 0; j < 8; j++) acc[i][j] = 0.f;
    const float* wbase = Wt + tj * 8;
#pragma unroll 2
    for (int k = 0; k < K; k += 4) {
        float4 xv[NE];
#pragma unroll
        for (int i = 0; i < NE; i++)
            xv[i] = *(const float4*)(sIn + (te + i * NT) * SX + k);
#pragma unroll
        for (int kk = 0; kk < 4; kk++) {
            float4 w0 = *(const float4*)(wbase + (k + kk) * NJ);
            float4 w1 = *(const float4*)(wbase + (k + kk) * NJ + 4);
#pragma unroll
            for (int i = 0; i < NE; i++)
                fma8(acc[i], (&xv[i].x)[kk], w0, w1);
        }
    }
}

// ---------------- prep: transpose/split weights, combine LSTM biases ----------------
#define PREP_TOTAL (16384 + 512 + 16384 + 8192 + 16384 + 16384 + 256 + 8192 + 16384)
__global__ void k_prep(const float* __restrict__ w1, const float* __restrict__ w2,
                       const float* __restrict__ w3, const float* __restrict__ wih,
                       const float* __restrict__ whh, const float* __restrict__ bih,
                       const float* __restrict__ bhh, const float* __restrict__ r1,
                       const float* __restrict__ r2) {
    int i = blockIdx.x * 256 + threadIdx.x;
    // w1 is [128 out][132 in]; in-dims: 0..63 h[row], 64..127 h[col], 128..131 ea
    if (i < 16384) {
        int j = i & 255, k = i >> 8;   // k<64
        g_wp[k * 256 + j] = (j < 128) ? w1[j * 132 + k] : w1[(j - 128) * 132 + 64 + k];
        return;
    }
    i -= 16384;
    if (i < 512)   { int k = i >> 7, j = i & 127; g_w1ct[k * 128 + j] = w1[j * 132 + 128 + k]; return; }
    i -= 512;
    if (i < 16384) { int j = i / 128, k = i % 128; g_w2t[k * 128 + j] = w2[i]; return; }
    i -= 16384;
    if (i < 8192)  { int j = i / 128, k = i % 128; g_w3t[k * 64 + j] = w3[i]; return; }
    i -= 8192;
    if (i < 16384) { int j = i / 64, k = i % 64; g_wg[k * 256 + j] = wih[i]; return; }
    i -= 16384;
    if (i < 16384) { int j = i / 64, k = i % 64; g_wg[(64 + k) * 256 + j] = whh[i]; return; }
    i -= 16384;
    if (i < 256)   { g_bg[i] = bih[i] + bhh[i]; return; }
    i -= 256;
    if (i < 8192)  { int j = i / 64, k = i % 64; g_ro1t[k * 128 + j] = r1[i]; return; }
    i -= 8192;
    if (i < 16384) { int j = i / 128, k = i % 128; g_ro2t[k * 128 + j] = r2[i]; return; }
}

// eaw[e][j] = b1[j] + sum_{k<4} ea[e][k] * W1c[j][k]   (step-invariant)
__global__ void k_eaw(const float* __restrict__ ea, const float* __restrict__ b1) {
    int gid = blockIdx.x * 256 + threadIdx.x;   // EEDGE*16 threads
    int e = gid >> 4, jg = gid & 15;
    float4 a = *(const float4*)(ea + (size_t)e * 4);
    float o[8];
    float4 bb0 = *(const float4*)(b1 + jg * 8);
    float4 bb1 = *(const float4*)(b1 + jg * 8 + 4);
    o[0] = bb0.x; o[1] = bb0.y; o[2] = bb0.z; o[3] = bb0.w;
    o[4] = bb1.x; o[5] = bb1.y; o[6] = bb1.z; o[7] = bb1.w;
#pragma unroll
    for (int k = 0; k < 4; k++) {
        float av = (&a.x)[k];
        float4 w0 = *(const float4*)(g_w1ct + k * 128 + jg * 8);
        float4 w1 = *(const float4*)(g_w1ct + k * 128 + jg * 8 + 4);
        fma8(o, av, w0, w1);
    }
    float* dst = g_eaw + (size_t)e * 128 + jg * 8;
#pragma unroll
    for (int j = 0; j < 8; j++) dst[j] = o[j];
}

// init h/c/nm and the initial projection P(h0).
// h0: zeros except factors have h0[.,0]=1 -> P[f] = g_wp row 0; P[node]=0.
__global__ void k_init() {
    int i = blockIdx.x * 256 + threadIdx.x;   // SSEG*256 threads
    if (i < SSEG * SD) {
        g_c[i] = 0.f;
        g_nm[i] = 0.f;
        int s = i >> 6, d = i & 63;
        g_h[i] = (s >= NNODES && d == 0) ? 1.f : 0.f;
    }
    if (i < SSEG * 256) {
        int s = i >> 8, j = i & 255;
        g_p[i] = (s >= NNODES) ? g_wp[j] : 0.f;
    }
}

// ---------------- edge MLP + scatter (32 edges / block, 128 threads) ----------------
// Layer 1 is now gather-add-relu of precomputed projections (no GEMM).
__global__ __launch_bounds__(128, 6) void k_edge(const int* __restrict__ row,
                                                 const int* __restrict__ col,
                                                 const float* __restrict__ b2,
                                                 const float* __restrict__ b3) {
    __shared__ float sH[32 * 132];   // relu-out of layer 1
    __shared__ float sX2[32 * 132];  // relu-out of layer 2
    __shared__ int sRow[32];
    __shared__ int sCol[32];
    const int tid = threadIdx.x;
    const int e0 = blockIdx.x * 32;

    if (tid < 32) sCol[tid] = col[e0 + tid];
    else if (tid < 64) sRow[tid - 32] = row[e0 + tid - 32];
    __syncthreads();

    // layer 1: relu(P1[row] + P2[col] + eaw[e])
    for (int u = tid; u < 32 * 32; u += 128) {
        int el = u >> 5, part = u & 31;     // part*4 = output j (0..124)
        const float* p1 = g_p + (size_t)sRow[el] * 256 + part * 4;
        const float* p2 = g_p + (size_t)sCol[el] * 256 + 128 + part * 4;
        const float* pe = g_eaw + (size_t)(e0 + el) * 128 + part * 4;
        float4 a = *(const float4*)p1;
        float4 b = *(const float4*)p2;
        float4 z = *(const float4*)pe;
        float4 r;
        r.x = fmaxf(a.x + b.x + z.x, 0.f);
        r.y = fmaxf(a.y + b.y + z.y, 0.f);
        r.z = fmaxf(a.z + b.z + z.z, 0.f);
        r.w = fmaxf(a.w + b.w + z.w, 0.f);
        *(float4*)(sH + el * 132 + part * 4) = r;
    }
    __syncthreads();

    // layer 2: 128 -> 128, relu
    {
        const int te = tid & 7, tj = tid >> 3;
        float acc[4][8];
        tile_gemm<4, 8, HM, HM, 132>(sH, g_w2t, te, tj, acc);
        float4 bb0 = *(const float4*)(b2 + tj * 8);
        float4 bb1 = *(const float4*)(b2 + tj * 8 + 4);
        float bv[8] = {bb0.x, bb0.y, bb0.z, bb0.w, bb1.x, bb1.y, bb1.z, bb1.w};
#pragma unroll
        for (int i = 0; i < 4; i++) {
            float* dst = sX2 + (te + i * 8) * 132 + tj * 8;
#pragma unroll
            for (int j = 0; j < 8; j++) dst[j] = fmaxf(acc[i][j] + bv[j], 0.f);
        }
    }
    __syncthreads();

    // layer 3: 128 -> 64, + scatter-add into nm[col]
    {
        const int te = tid & 15, tj = tid >> 4;  // 16 x (2 edges), 8 x (8 outputs)
        float acc[2][8];
        tile_gemm<2, 16, HM, SD, 132>(sX2, g_w3t, te, tj, acc);
        float4 bb0 = *(const float4*)(b3 + tj * 8);
        float4 bb1 = *(const float4*)(b3 + tj * 8 + 4);
        float bv[8] = {bb0.x, bb0.y, bb0.z, bb0.w, bb1.x, bb1.y, bb1.z, bb1.w};
#pragma unroll
        for (int i = 0; i < 2; i++) {
            float* dst = g_nm + (size_t)sCol[te + i * 16] * SD + tj * 8;
#pragma unroll
            for (int j = 0; j < 8; j++) atomicAdd(dst + j, acc[i][j] + bv[j]);
        }
    }
}

// ------- fused LSTM cell + nm re-zero + NEXT-STEP PROJECTION (32 segs, 256 thr) -------
__global__ __launch_bounds__(256, 2) void k_lstm_proj() {
    __shared__ float sMem[32 * 264];  // sX (32x132) then aliased as sG (32x264)
    __shared__ float sHn[32 * 68];    // h_new staging for the projection GEMM
    float* const sX = sMem;
    float* const sG = sMem;
    const int tid = threadIdx.x;
    const int s0 = blockIdx.x * 32;
    const int te = tid & 7, tj = tid >> 3;

    // load [nm | h] for 32 segments (zero-pad tail)
    for (int u = tid; u < 32 * 32; u += 256) {
        int el = u >> 5, part = u & 31;
        int s = s0 + el;
        float4 v = make_float4(0.f, 0.f, 0.f, 0.f);
        if (s < SSEG) {
            const float* src = (part < 16) ? (g_nm + (size_t)s * SD + part * 4)
                                           : (g_h + (size_t)s * SD + (part - 16) * 4);
            v = *(const float4*)src;
        }
        *(float4*)(sX + el * 132 + part * 4) = v;
    }
    __syncthreads();

    // re-zero the nm rows we just consumed
    for (int u = tid; u < 32 * 16; u += 256) {
        int el = u >> 4, part = u & 15;
        int s = s0 + el;
        if (s < SSEG)
            *(float4*)(g_nm + (size_t)s * SD + part * 4) = make_float4(0.f, 0.f, 0.f, 0.f);
    }

    // gates GEMM: [32 x 128] @ [128 x 256]
    {
        float acc[4][8];
        tile_gemm<4, 8, 2 * SD, 4 * SD, 132>(sX, g_wg, te, tj, acc);
        float4 bb0 = *(const float4*)(g_bg + tj * 8);
        float4 bb1 = *(const float4*)(g_bg + tj * 8 + 4);
        float bv[8] = {bb0.x, bb0.y, bb0.z, bb0.w, bb1.x, bb1.y, bb1.z, bb1.w};
        __syncthreads();  // all sX reads done before aliasing the buffer as sG
#pragma unroll
        for (int i = 0; i < 4; i++)
#pragma unroll
            for (int j = 0; j < 8; j++)
                sG[(te + i * 8) * 264 + tj * 8 + j] = acc[i][j] + bv[j];
    }
    __syncthreads();

    // elementwise LSTM; stage h_new into sHn for the projection
    for (int u = tid; u < 32 * 64; u += 256) {
        int el = u >> 6, d = u & 63;
        int s = s0 + el;
        float hn = 0.f;
        if (s < SSEG) {
            float gi = sG[el * 264 + d];
            float gf = sG[el * 264 + 64 + d];
            float gg = sG[el * 264 + 128 + d];
            float go = sG[el * 264 + 192 + d];
            float c = g_c[(size_t)s * SD + d];
            float cn = sigm(gf) * c + sigm(gi) * tanhf(gg);
            g_c[(size_t)s * SD + d] = cn;
            hn = sigm(go) * tanhf(cn);
            g_h[(size_t)s * SD + d] = hn;
        }
        sHn[el * 68 + d] = hn;
    }
    __syncthreads();

    // projection for next step: P = h_new @ g_wp  ([32 x 64] @ [64 x 256])
    {
        float acc[4][8];
        tile_gemm<4, 8, SD, 256, 68>(sHn, g_wp, te, tj, acc);
#pragma unroll
        for (int i = 0; i < 4; i++) {
            int s = s0 + te + i * 8;
            if (s < SSEG) {
                float* dst = g_p + (size_t)s * 256 + tj * 8;
                *(float4*)dst       = make_float4(acc[i][0], acc[i][1], acc[i][2], acc[i][3]);
                *(float4*)(dst + 4) = make_float4(acc[i][4], acc[i][5], acc[i][6], acc[i][7]);
            }
        }
    }
}

// ---------------- readout MLP + softmax (32 nodes / block, 128 threads) ----------------
__global__ __launch_bounds__(128) void k_readout(const float* __restrict__ b1,
                                                 const float* __restrict__ b2,
                                                 const float* __restrict__ w3,
                                                 const float* __restrict__ b3,
                                                 float* __restrict__ out) {
    __shared__ float sX[32 * 68];
    __shared__ float sA[32 * 132];
    __shared__ float sB[32 * 132];
    const int tid = threadIdx.x;
    const int n0 = blockIdx.x * 32;

    for (int u = tid; u < 32 * 16; u += 128) {
        int el = u >> 4, part = u & 15;
        int n = n0 + el;
        float4 v = make_float4(0.f, 0.f, 0.f, 0.f);
        if (n < NNODES) v = *(const float4*)(g_h + (size_t)n * SD + part * 4);
        *(float4*)(sX + el * 68 + part * 4) = v;
    }
    __syncthreads();
    {
        const int te = tid & 7, tj = tid >> 3;
        float acc[4][8];
        tile_gemm<4, 8, SD, HM, 68>(sX, g_ro1t, te, tj, acc);
        float4 bb0 = *(const float4*)(b1 + tj * 8);
        float4 bb1 = *(const float4*)(b1 + tj * 8 + 4);
        float bv[8] = {bb0.x, bb0.y, bb0.z, bb0.w, bb1.x, bb1.y, bb1.z, bb1.w};
#pragma unroll
        for (int i = 0; i < 4; i++) {
            float* dst = sA + (te + i * 8) * 132 + tj * 8;
#pragma unroll
            for (int j = 0; j < 8; j++) dst[j] = fmaxf(acc[i][j] + bv[j], 0.f);
        }
    }
    __syncthreads();
    {
        const int te = tid & 7, tj = tid >> 3;
        float acc[4][8];
        tile_gemm<4, 8, HM, HM, 132>(sA, g_ro2t, te, tj, acc);
        float4 bb0 = *(const float4*)(b2 + tj * 8);
        float4 bb1 = *(const float4*)(b2 + tj * 8 + 4);
        float bv[8] = {bb0.x, bb0.y, bb0.z, bb0.w, bb1.x, bb1.y, bb1.z, bb1.w};
#pragma unroll
        for (int i = 0; i < 4; i++) {
            float* dst = sB + (te + i * 8) * 132 + tj * 8;
#pragma unroll
            for (int j = 0; j < 8; j++) dst[j] = fmaxf(acc[i][j] + bv[j], 0.f);
        }
    }
    __syncthreads();
    if (tid < 32) {
        int n = n0 + tid;
        if (n < NNODES) {
            float l0 = b3[0], l1 = b3[1];
            const float* x = sB + tid * 132;
#pragma unroll 4
            for (int k = 0; k < HM; k++) {
                l0 = fmaf(x[k], w3[k], l0);
                l1 = fmaf(x[k], w3[HM + k], l1);
            }
            float m = fmaxf(l0, l1);
            float e0 = expf(l0 - m), e1 = expf(l1 - m);
            float inv = 1.f / (e0 + e1);
            out[(size_t)n * 2 + 0] = e0 * inv;
            out[(size_t)n * 2 + 1] = e1 * inv;
        }
    }
}

// ---------------- launch ----------------
extern "C" void kernel_launch(void* const* d_in, const int* in_sizes, int n_in,
                              void* d_out, int out_size) {
    (void)out_size;
    int base = 3;
    if (n_in >= 21 && in_sizes[3] == 1 && in_sizes[4] == 1) base = 5;

    const int* row = (const int*)d_in[0];
    const int* col = (const int*)d_in[1];
    const float* ea = (const float*)d_in[2];
    const float* mp_w1 = (const float*)d_in[base + 0];
    const float* mp_b1 = (const float*)d_in[base + 1];
    const float* mp_w2 = (const float*)d_in[base + 2];
    const float* mp_b2 = (const float*)d_in[base + 3];
    const float* mp_w3 = (const float*)d_in[base + 4];
    const float* mp_b3 = (const float*)d_in[base + 5];
    const float* w_ih  = (const float*)d_in[base + 6];
    const float* w_hh  = (const float*)d_in[base + 7];
    const float* b_ih  = (const float*)d_in[base + 8];
    const float* b_hh  = (const float*)d_in[base + 9];
    const float* ro_w1 = (const float*)d_in[base + 10];
    const float* ro_b1 = (const float*)d_in[base + 11];
    const float* ro_w2 = (const float*)d_in[base + 12];
    const float* ro_b2 = (const float*)d_in[base + 13];
    const float* ro_w3 = (const float*)d_in[base + 14];
    const float* ro_b3 = (const float*)d_in[base + 15];
    float* out = (float*)d_out;

    k_prep<<<(PREP_TOTAL + 255) / 256, 256>>>(mp_w1, mp_w2, mp_w3, w_ih, w_hh,
                                              b_ih, b_hh, ro_w1, ro_w2);
    k_eaw<<<EEDGE * 16 / 256, 256>>>(ea, mp_b1);
    k_init<<<(SSEG * 256 + 255) / 256, 256>>>();

    for (int t = 0; t < NSTEPS; t++) {
        k_edge<<<EEDGE / 32, 128>>>(row, col, mp_b2, mp_b3);
        k_lstm_proj<<<(SSEG + 31) / 32, 256>>>();
    }

    k_readout<<<(NNODES + 31) / 32, 128>>>(ro_b1, ro_b2, ro_w3, ro_b3, out);
}

// round 10
// speedup vs baseline: 1.7747x; 1.0371x over previous
#include <cuda_runtime.h>
#include <math.h>

// Problem constants (fixed-shape problem)
#define NNODES 10000
#define NFACT  20000
#define SSEG   30000      // NNODES + NFACT
#define EEDGE  80000      // 4 * NFACT
#define SD     64         // STATE_DIM == MSG_DIM
#define HM     128        // HID_MSG == HID_RO
#define NSTEPS 10
#define WPAD   264

// ---------------- persistent device scratch (no allocation allowed) ----------------
__device__ float g_h[SSEG * SD];
__device__ float g_c[SSEG * SD];
__device__ float g_nm[SSEG * SD];
__device__ float g_p[SSEG * 256];               // [P1(128) | P2(128)] per segment
__device__ float g_eaw[EEDGE * HM];             // W1c @ edge_attr + b1, per edge (step-invariant)
__device__ float g_wp[SD * 256 + WPAD];         // [k=64][j=256]: j<128 -> W1a^T, j>=128 -> W1b^T
__device__ float g_w1ct[4 * HM];                // [k=4][j=128] = W1c^T
__device__ float g_w2t[HM * HM + WPAD];         // [128][128] = mp_w2^T
__device__ float g_w3t[HM * SD + WPAD];         // [128][64]  = mp_w3^T
__device__ float g_wg[(2 * SD) * (4 * SD) + WPAD]; // [128][256]: rows 0..63 w_ih^T, 64..127 w_hh^T
__device__ float g_bg[4 * SD];                  // b_ih + b_hh
__device__ float g_ro1t[SD * HM + WPAD];        // [64][128]  = ro_w1^T
__device__ float g_ro2t[HM * HM + WPAD];        // [128][128] = ro_w2^T

__device__ __forceinline__ float sigm(float x) { return 1.f / (1.f + __expf(-x)); }

__device__ __forceinline__ void fma8(float* a, float x, const float4 w0, const float4 w1) {
    a[0] = fmaf(x, w0.x, a[0]); a[1] = fmaf(x, w0.y, a[1]);
    a[2] = fmaf(x, w0.z, a[2]); a[3] = fmaf(x, w0.w, a[3]);
    a[4] = fmaf(x, w1.x, a[4]); a[5] = fmaf(x, w1.y, a[5]);
    a[6] = fmaf(x, w1.z, a[6]); a[7] = fmaf(x, w1.w, a[7]);
}

// Register-tiled GEMM. Each thread computes NE interleaved rows (te + i*NT) x 8 cols.
// sIn: shared, row stride SX floats. Wt: global, layout [K][NJ].
template <int NE, int NT, int K, int NJ, int SX>
__device__ __forceinline__ void tile_gemm(const float* sIn, const float* __restrict__ Wt,
                                          int te, int tj, float acc[][8]) {
#pragma unroll
    for (int i = 0; i < NE; i++)
#pragma unroll
        for (int j = 0; j < 8; j++) acc[i][j] = 0.f;
    const float* wbase = Wt + tj * 8;
#pragma unroll 2
    for (int k = 0; k < K; k += 4) {
        float4 xv[NE];
#pragma unroll
        for (int i = 0; i < NE; i++)
            xv[i] = *(const float4*)(sIn + (te + i * NT) * SX + k);
#pragma unroll
        for (int kk = 0; kk < 4; kk++) {
            float4 w0 = *(const float4*)(wbase + (k + kk) * NJ);
            float4 w1 = *(const float4*)(wbase + (k + kk) * NJ + 4);
#pragma unroll
            for (int i = 0; i < NE; i++)
                fma8(acc[i], (&xv[i].x)[kk], w0, w1);
        }
    }
}

// ---------------- prep: transpose/split weights, combine LSTM biases ----------------
#define PREP_TOTAL (16384 + 512 + 16384 + 8192 + 16384 + 16384 + 256 + 8192 + 16384)
__global__ void k_prep(const float* __restrict__ w1, const float* __restrict__ w2,
                       const float* __restrict__ w3, const float* __restrict__ wih,
                       const float* __restrict__ whh, const float* __restrict__ bih,
                       const float* __restrict__ bhh, const float* __restrict__ r1,
                       const float* __restrict__ r2) {
    int i = blockIdx.x * 256 + threadIdx.x;
    // w1 is [128 out][132 in]; in-dims: 0..63 h[row], 64..127 h[col], 128..131 ea
    if (i < 16384) {
        int j = i & 255, k = i >> 8;   // k<64
        g_wp[k * 256 + j] = (j < 128) ? w1[j * 132 + k] : w1[(j - 128) * 132 + 64 + k];
        return;
    }
    i -= 16384;
    if (i < 512)   { int k = i >> 7, j = i & 127; g_w1ct[k * 128 + j] = w1[j * 132 + 128 + k]; return; }
    i -= 512;
    if (i < 16384) { int j = i / 128, k = i % 128; g_w2t[k * 128 + j] = w2[i]; return; }
    i -= 16384;
    if (i < 8192)  { int j = i / 128, k = i % 128; g_w3t[k * 64 + j] = w3[i]; return; }
    i -= 8192;
    if (i < 16384) { int j = i / 64, k = i % 64; g_wg[k * 256 + j] = wih[i]; return; }
    i -= 16384;
    if (i < 16384) { int j = i / 64, k = i % 64; g_wg[(64 + k) * 256 + j] = whh[i]; return; }
    i -= 16384;
    if (i < 256)   { g_bg[i] = bih[i] + bhh[i]; return; }
    i -= 256;
    if (i < 8192)  { int j = i / 64, k = i % 64; g_ro1t[k * 128 + j] = r1[i]; return; }
    i -= 8192;
    if (i < 16384) { int j = i / 128, k = i % 128; g_ro2t[k * 128 + j] = r2[i]; return; }
}

// eaw[e][j] = b1[j] + sum_{k<4} ea[e][k] * W1c[j][k]   (step-invariant)
__global__ void k_eaw(const float* __restrict__ ea, const float* __restrict__ b1) {
    int gid = blockIdx.x * 256 + threadIdx.x;   // EEDGE*16 threads
    int e = gid >> 4, jg = gid & 15;
    float4 a = *(const float4*)(ea + (size_t)e * 4);
    float o[8];
    float4 bb0 = *(const float4*)(b1 + jg * 8);
    float4 bb1 = *(const float4*)(b1 + jg * 8 + 4);
    o[0] = bb0.x; o[1] = bb0.y; o[2] = bb0.z; o[3] = bb0.w;
    o[4] = bb1.x; o[5] = bb1.y; o[6] = bb1.z; o[7] = bb1.w;
#pragma unroll
    for (int k = 0; k < 4; k++) {
        float av = (&a.x)[k];
        float4 w0 = *(const float4*)(g_w1ct + k * 128 + jg * 8);
        float4 w1 = *(const float4*)(g_w1ct + k * 128 + jg * 8 + 4);
        fma8(o, av, w0, w1);
    }
    float* dst = g_eaw + (size_t)e * 128 + jg * 8;
#pragma unroll
    for (int j = 0; j < 8; j++) dst[j] = o[j];
}

// init h/c/nm and the initial projection P(h0).
__global__ void k_init() {
    int i = blockIdx.x * 256 + threadIdx.x;   // SSEG*256 threads
    if (i < SSEG * SD) {
        g_c[i] = 0.f;
        g_nm[i] = 0.f;
        int s = i >> 6, d = i & 63;
        g_h[i] = (s >= NNODES && d == 0) ? 1.f : 0.f;
    }
    if (i < SSEG * 256) {
        int s = i >> 8, j = i & 255;
        g_p[i] = (s >= NNODES) ? g_wp[j] : 0.f;
    }
}

// ---------------- edge MLP + scatter (64 edges / block, 128 threads) ----------------
// Layer 1: gather-add-relu of precomputed projections (no GEMM).
// Single smem buffer reused L1-out -> L2-out via register-resident accumulators.
__global__ __launch_bounds__(128, 4) void k_edge(const int* __restrict__ row,
                                                 const int* __restrict__ col,
                                                 const float* __restrict__ b2,
                                                 const float* __restrict__ b3) {
    __shared__ float sBuf[64 * 132];   // 33.8 KB, aliased across layers
    __shared__ int sRow[64];
    __shared__ int sCol[64];
    const int tid = threadIdx.x;
    const int e0 = blockIdx.x * 64;

    if (tid < 64) sCol[tid] = col[e0 + tid];
    else sRow[tid - 64] = row[e0 + tid - 64];
    __syncthreads();

    // layer 1: relu(P1[row] + P2[col] + eaw[e])  -> sBuf
    for (int u = tid; u < 64 * 32; u += 128) {
        int el = u >> 5, part = u & 31;     // part*4 = output j (0..124)
        const float* p1 = g_p + (size_t)sRow[el] * 256 + part * 4;
        const float* p2 = g_p + (size_t)sCol[el] * 256 + 128 + part * 4;
        const float* pe = g_eaw + (size_t)(e0 + el) * 128 + part * 4;
        float4 a = *(const float4*)p1;
        float4 b = *(const float4*)p2;
        float4 z = *(const float4*)pe;
        float4 r;
        r.x = fmaxf(a.x + b.x + z.x, 0.f);
        r.y = fmaxf(a.y + b.y + z.y, 0.f);
        r.z = fmaxf(a.z + b.z + z.z, 0.f);
        r.w = fmaxf(a.w + b.w + z.w, 0.f);
        *(float4*)(sBuf + el * 132 + part * 4) = r;
    }
    __syncthreads();

    // layer 2: 128 -> 128, relu; NE=8 halves weight traffic per FMA.
    // Accumulate in regs, sync, then overwrite sBuf in place.
    {
        const int te = tid & 7, tj = tid >> 3;   // 8 x (8 edges), 16 x (8 cols)
        float acc[8][8];
        tile_gemm<8, 8, HM, HM, 132>(sBuf, g_w2t, te, tj, acc);
        float4 bb0 = *(const float4*)(b2 + tj * 8);
        float4 bb1 = *(const float4*)(b2 + tj * 8 + 4);
        float bv[8] = {bb0.x, bb0.y, bb0.z, bb0.w, bb1.x, bb1.y, bb1.z, bb1.w};
        __syncthreads();   // all layer-1 reads complete before in-place overwrite
#pragma unroll
        for (int i = 0; i < 8; i++) {
            float* dst = sBuf + (te + i * 8) * 132 + tj * 8;
#pragma unroll
            for (int j = 0; j < 8; j++) dst[j] = fmaxf(acc[i][j] + bv[j], 0.f);
        }
    }
    __syncthreads();

    // layer 3: 128 -> 64, + scatter-add into nm[col]
    {
        const int te = tid & 15, tj = tid >> 4;  // 16 x (4 edges), 8 x (8 outputs)
        float acc[4][8];
        tile_gemm<4, 16, HM, SD, 132>(sBuf, g_w3t, te, tj, acc);
        float4 bb0 = *(const float4*)(b3 + tj * 8);
        float4 bb1 = *(const float4*)(b3 + tj * 8 + 4);
        float bv[8] = {bb0.x, bb0.y, bb0.z, bb0.w, bb1.x, bb1.y, bb1.z, bb1.w};
#pragma unroll
        for (int i = 0; i < 4; i++) {
            float* dst = g_nm + (size_t)sCol[te + i * 16] * SD + tj * 8;
#pragma unroll
            for (int j = 0; j < 8; j++) atomicAdd(dst + j, acc[i][j] + bv[j]);
        }
    }
}

// ------- fused LSTM cell + nm re-zero + next-step projection (32 segs, 256 thr) -------
__global__ __launch_bounds__(256, 3) void k_lstm_proj() {
    __shared__ float sMem[32 * 264];  // sX (32x132) then aliased as sG (32x264)
    __shared__ float sHn[32 * 68];    // h_new staging for the projection GEMM
    float* const sX = sMem;
    float* const sG = sMem;
    const int tid = threadIdx.x;
    const int s0 = blockIdx.x * 32;
    const int te = tid & 7, tj = tid >> 3;

    // load [nm | h] for 32 segments (zero-pad tail)
    for (int u = tid; u < 32 * 32; u += 256) {
        int el = u >> 5, part = u & 31;
        int s = s0 + el;
        float4 v = make_float4(0.f, 0.f, 0.f, 0.f);
        if (s < SSEG) {
            const float* src = (part < 16) ? (g_nm + (size_t)s * SD + part * 4)
                                           : (g_h + (size_t)s * SD + (part - 16) * 4);
            v = *(const float4*)src;
        }
        *(float4*)(sX + el * 132 + part * 4) = v;
    }
    __syncthreads();

    // re-zero the nm rows we just consumed
    for (int u = tid; u < 32 * 16; u += 256) {
        int el = u >> 4, part = u & 15;
        int s = s0 + el;
        if (s < SSEG)
            *(float4*)(g_nm + (size_t)s * SD + part * 4) = make_float4(0.f, 0.f, 0.f, 0.f);
    }

    // gates GEMM: [32 x 128] @ [128 x 256]
    {
        float acc[4][8];
        tile_gemm<4, 8, 2 * SD, 4 * SD, 132>(sX, g_wg, te, tj, acc);
        float4 bb0 = *(const float4*)(g_bg + tj * 8);
        float4 bb1 = *(const float4*)(g_bg + tj * 8 + 4);
        float bv[8] = {bb0.x, bb0.y, bb0.z, bb0.w, bb1.x, bb1.y, bb1.z, bb1.w};
        __syncthreads();  // all sX reads done before aliasing the buffer as sG
#pragma unroll
        for (int i = 0; i < 4; i++)
#pragma unroll
            for (int j = 0; j < 8; j++)
                sG[(te + i * 8) * 264 + tj * 8 + j] = acc[i][j] + bv[j];
    }
    __syncthreads();

    // elementwise LSTM; stage h_new into sHn for the projection
    for (int u = tid; u < 32 * 64; u += 256) {
        int el = u >> 6, d = u & 63;
        int s = s0 + el;
        float hn = 0.f;
        if (s < SSEG) {
            float gi = sG[el * 264 + d];
            float gf = sG[el * 264 + 64 + d];
            float gg = sG[el * 264 + 128 + d];
            float go = sG[el * 264 + 192 + d];
            float c = g_c[(size_t)s * SD + d];
            float cn = sigm(gf) * c + sigm(gi) * tanhf(gg);
            g_c[(size_t)s * SD + d] = cn;
            hn = sigm(go) * tanhf(cn);
            g_h[(size_t)s * SD + d] = hn;
        }
        sHn[el * 68 + d] = hn;
    }
    __syncthreads();

    // projection for next step: P = h_new @ g_wp  ([32 x 64] @ [64 x 256])
    {
        float acc[4][8];
        tile_gemm<4, 8, SD, 256, 68>(sHn, g_wp, te, tj, acc);
#pragma unroll
        for (int i = 0; i < 4; i++) {
            int s = s0 + te + i * 8;
            if (s < SSEG) {
                float* dst = g_p + (size_t)s * 256 + tj * 8;
                *(float4*)dst       = make_float4(acc[i][0], acc[i][1], acc[i][2], acc[i][3]);
                *(float4*)(dst + 4) = make_float4(acc[i][4], acc[i][5], acc[i][6], acc[i][7]);
            }
        }
    }
}

// ---------------- readout MLP + softmax (32 nodes / block, 128 threads) ----------------
__global__ __launch_bounds__(128) void k_readout(const float* __restrict__ b1,
                                                 const float* __restrict__ b2,
                                                 const float* __restrict__ w3,
                                                 const float* __restrict__ b3,
                                                 float* __restrict__ out) {
    __shared__ float sX[32 * 68];
    __shared__ float sA[32 * 132];
    __shared__ float sB[32 * 132];
    const int tid = threadIdx.x;
    const int n0 = blockIdx.x * 32;

    for (int u = tid; u < 32 * 16; u += 128) {
        int el = u >> 4, part = u & 15;
        int n = n0 + el;
        float4 v = make_float4(0.f, 0.f, 0.f, 0.f);
        if (n < NNODES) v = *(const float4*)(g_h + (size_t)n * SD + part * 4);
        *(float4*)(sX + el * 68 + part * 4) = v;
    }
    __syncthreads();
    {
        const int te = tid & 7, tj = tid >> 3;
        float acc[4][8];
        tile_gemm<4, 8, SD, HM, 68>(sX, g_ro1t, te, tj, acc);
        float4 bb0 = *(const float4*)(b1 + tj * 8);
        float4 bb1 = *(const float4*)(b1 + tj * 8 + 4);
        float bv[8] = {bb0.x, bb0.y, bb0.z, bb0.w, bb1.x, bb1.y, bb1.z, bb1.w};
#pragma unroll
        for (int i = 0; i < 4; i++) {
            float* dst = sA + (te + i * 8) * 132 + tj * 8;
#pragma unroll
            for (int j = 0; j < 8; j++) dst[j] = fmaxf(acc[i][j] + bv[j], 0.f);
        }
    }
    __syncthreads();
    {
        const int te = tid & 7, tj = tid >> 3;
        float acc[4][8];
        tile_gemm<4, 8, HM, HM, 132>(sA, g_ro2t, te, tj, acc);
        float4 bb0 = *(const float4*)(b2 + tj * 8);
        float4 bb1 = *(const float4*)(b2 + tj * 8 + 4);
        float bv[8] = {bb0.x, bb0.y, bb0.z, bb0.w, bb1.x, bb1.y, bb1.z, bb1.w};
#pragma unroll
        for (int i = 0; i < 4; i++) {
            float* dst = sB + (te + i * 8) * 132 + tj * 8;
#pragma unroll
            for (int j = 0; j < 8; j++) dst[j] = fmaxf(acc[i][j] + bv[j], 0.f);
        }
    }
    __syncthreads();
    if (tid < 32) {
        int n = n0 + tid;
        if (n < NNODES) {
            float l0 = b3[0], l1 = b3[1];
            const float* x = sB + tid * 132;
#pragma unroll 4
            for (int k = 0; k < HM; k++) {
                l0 = fmaf(x[k], w3[k], l0);
                l1 = fmaf(x[k], w3[HM + k], l1);
            }
            float m = fmaxf(l0, l1);
            float e0 = expf(l0 - m), e1 = expf(l1 - m);
            float inv = 1.f / (e0 + e1);
            out[(size_t)n * 2 + 0] = e0 * inv;
            out[(size_t)n * 2 + 1] = e1 * inv;
        }
    }
}

// ---------------- launch ----------------
extern "C" void kernel_launch(void* const* d_in, const int* in_sizes, int n_in,
                              void* d_out, int out_size) {
    (void)out_size;
    int base = 3;
    if (n_in >= 21 && in_sizes[3] == 1 && in_sizes[4] == 1) base = 5;

    const int* row = (const int*)d_in[0];
    const int* col = (const int*)d_in[1];
    const float* ea = (const float*)d_in[2];
    const float* mp_w1 = (const float*)d_in[base + 0];
    const float* mp_b1 = (const float*)d_in[base + 1];
    const float* mp_w2 = (const float*)d_in[base + 2];
    const float* mp_b2 = (const float*)d_in[base + 3];
    const float* mp_w3 = (const float*)d_in[base + 4];
    const float* mp_b3 = (const float*)d_in[base + 5];
    const float* w_ih  = (const float*)d_in[base + 6];
    const float* w_hh  = (const float*)d_in[base + 7];
    const float* b_ih  = (const float*)d_in[base + 8];
    const float* b_hh  = (const float*)d_in[base + 9];
    const float* ro_w1 = (const float*)d_in[base + 10];
    const float* ro_b1 = (const float*)d_in[base + 11];
    const float* ro_w2 = (const float*)d_in[base + 12];
    const float* ro_b2 = (const float*)d_in[base + 13];
    const float* ro_w3 = (const float*)d_in[base + 14];
    const float* ro_b3 = (const float*)d_in[base + 15];
    float* out = (float*)d_out;

    k_prep<<<(PREP_TOTAL + 255) / 256, 256>>>(mp_w1, mp_w2, mp_w3, w_ih, w_hh,
                                              b_ih, b_hh, ro_w1, ro_w2);
    k_eaw<<<EEDGE * 16 / 256, 256>>>(ea, mp_b1);
    k_init<<<(SSEG * 256 + 255) / 256, 256>>>();

    for (int t = 0; t < NSTEPS; t++) {
        k_edge<<<EEDGE / 64, 128>>>(row, col, mp_b2, mp_b3);
        k_lstm_proj<<<(SSEG + 31) / 32, 256>>>();
    }

    k_readout<<<(NNODES + 31) / 32, 128>>>(ro_b1, ro_b2, ro_w3, ro_b3, out);
}